// round 8
// baseline (speedup 1.0000x reference)
#include <cuda_runtime.h>
#include <cstdint>

// Problem constants (dataset-fixed: IN=(32,3,512,512), OUT=256, scale=0.5)
#define BC      96
#define IN_HW   512
#define OUT_HW  256
#define TOH     16            // oh rows per block (two 8-row halves)
#define RPH     8             // rows per half
#define MAX_T   12
#define HALFP   260           // odd-column region offset, in 8-byte units
#define MIDW    520           // mid2 row length in 8-byte units

typedef unsigned long long ull;

__device__ __forceinline__ ull pack2(float x, float y) {
    ull r; asm("mov.b64 %0, {%1, %2};" : "=l"(r) : "f"(x), "f"(y)); return r;
}
__device__ __forceinline__ void unpack2(ull v, float& x, float& y) {
    asm("mov.b64 {%0, %1}, %2;" : "=f"(x), "=f"(y) : "l"(v));
}
__device__ __forceinline__ void ffma2(ull& a, ull w, ull v) {
    asm("fma.rn.f32x2 %0, %1, %2, %0;" : "+l"(a) : "l"(w), "l"(v));
}
__device__ __forceinline__ ull fadd2(ull a, ull b) {
    ull r; asm("add.rn.f32x2 %0, %1, %2;" : "=l"(r) : "l"(a), "l"(b)); return r;
}

// even/odd split position (8-byte units): fixed-tap gathers become stride-1.
__device__ __forceinline__ int pos_of(int w) { return (w >> 1) + (w & 1) * HALFP; }

// ---------------------------------------------------------------------------
// Fused bicubic downsample. Block = 512 threads = one plane x 16 oh x full W.
// Phase 1 (H): per-half circular register window + FFMA2. On the fast path
//   (H fov linear AND H weights uniform across r -- checked from smem, free)
//   the 8 weights live in registers: ZERO shared loads in the inner loop.
// Phase 2 (W): per-thread register tables (from global, once), conflict-free
//   LDS.64 on packed row pairs, coalesced stores.
// ---------------------------------------------------------------------------
template<int TAPS>
__global__ __launch_bounds__(512, 3) void resize_fused(
    const ull*   __restrict__ in,     // (BC, IN_HW, 256) column pairs
    const float* __restrict__ wh, const int* __restrict__ fh,   // H tables
    const float* __restrict__ ww, const int* __restrict__ fw,   // W tables
    float*       __restrict__ out)    // (BC, OUT_HW, OUT_HW)
{
    __shared__ ull   mid2[TOH / 2][MIDW];     // packed row pairs, split layout
    __shared__ float hw_s[TAPS][TOH];         // H weights table
    __shared__ int   hf_s[TAPS][TOH];         // H fov table

    const int tid   = threadIdx.x;            // 0..511
    const int col   = tid & 255;              // owns input cols (2c, 2c+1)
    const int r0    = (tid >> 8) * RPH;       // first oh row of this half
    const int oh0   = blockIdx.x * TOH;
    const int plane = blockIdx.y;

    if (tid < TAPS * TOH) {
        const int t = tid / TOH, r = tid % TOH;
        hw_s[t][r] = wh[t * OUT_HW + oh0 + r];
        hf_s[t][r] = fh[t * OUT_HW + oh0 + r];
    }
    __syncthreads();

    // Fast iff H fov is linear (base + 2r + t) AND H weights are uniform in r.
    // Checked entirely from smem -- no extra global traffic.
    bool okp = true;
    if (tid < TAPS * TOH) {
        const int t = tid / TOH, r = tid % TOH;
        okp = (hf_s[t][r] == hf_s[0][0] + 2 * r + t)
           && (hw_s[t][r] == hw_s[t][0]);
    }
    const int fast = __syncthreads_and(okp);

    // Phase-2 per-thread tables (as in R6 -- never the bottleneck).
    ull pw[TAPS];
    int pr[TAPS];
    #pragma unroll
    for (int t = 0; t < TAPS; ++t) {
        const float w = ww[t * OUT_HW + col];
        pw[t] = pack2(w, w);
        pr[t] = pos_of(fw[t * OUT_HW + col]);
    }

    const ull* base = in + (size_t)plane * IN_HW * 256 + col;

    if (fast) {
        // -------- Phase 1 fast: register weights, circular window ---------
        ull hwr[TAPS];
        #pragma unroll
        for (int t = 0; t < TAPS; ++t) {
            const float w = hw_s[t][0];
            hwr[t] = pack2(w, w);
        }

        ull v[TAPS];
        const int b0 = hf_s[0][0] + 2 * r0;
        #pragma unroll
        for (int t = 0; t < TAPS; ++t)
            v[t] = base[(size_t)(b0 + t) * 256];

        ull stash = 0;
        #pragma unroll
        for (int j = 0; j < RPH; ++j) {
            ull a0 = 0, a1 = 0;
            ffma2(a0, hwr[0], v[(2 * j)     % TAPS]);
            ffma2(a1, hwr[1], v[(2 * j + 1) % TAPS]);
            if (j < RPH - 1) {                // refill the two consumed slots
                v[(2 * j)     % TAPS] = base[(size_t)(b0 + 2 * j + TAPS)     * 256];
                v[(2 * j + 1) % TAPS] = base[(size_t)(b0 + 2 * j + TAPS + 1) * 256];
            }
            #pragma unroll
            for (int t = 2; t < TAPS; ++t) {
                if (t & 1) ffma2(a1, hwr[t], v[(2 * j + t) % TAPS]);
                else       ffma2(a0, hwr[t], v[(2 * j + t) % TAPS]);
            }
            const ull acc = fadd2(a0, a1);    // (evenColVal, oddColVal)
            if ((j & 1) == 0) stash = acc;
            else {                            // repack across the row pair
                float ex, ey, ox, oy;
                unpack2(stash, ex, ey);
                unpack2(acc,   ox, oy);
                const int rp = (r0 >> 1) + (j >> 1);
                mid2[rp][col]         = pack2(ex, ox);
                mid2[rp][col + HALFP] = pack2(ey, oy);
            }
        }
    } else {
        // -------- Phase 1 generic (edge tiles with mirror folds) ----------
        float sx = 0.f, sy = 0.f;
        #pragma unroll
        for (int j = 0; j < RPH; ++j) {
            const int r = r0 + j;
            float ax = 0.f, ay = 0.f;
            #pragma unroll
            for (int t = 0; t < TAPS; ++t) {
                float x, y; unpack2(base[(size_t)hf_s[t][r] * 256], x, y);
                ax = fmaf(hw_s[t][r], x, ax);
                ay = fmaf(hw_s[t][r], y, ay);
            }
            if ((j & 1) == 0) { sx = ax; sy = ay; }
            else {
                const int rp = (r0 >> 1) + (j >> 1);
                mid2[rp][col]         = pack2(sx, ax);
                mid2[rp][col + HALFP] = pack2(sy, ay);
            }
        }
    }
    __syncthreads();

    // -------- Phase 2: W resize on packed row pairs --------
    float* ob = out + ((size_t)plane * OUT_HW + oh0 + r0) * OUT_HW + col;
    #pragma unroll
    for (int p = 0; p < RPH / 2; ++p) {
        const int rp = (r0 >> 1) + p;
        ull a0 = 0, a1 = 0;
        #pragma unroll
        for (int t = 0; t < TAPS; ++t) {
            if (t & 1) ffma2(a1, pw[t], mid2[rp][pr[t]]);
            else       ffma2(a0, pw[t], mid2[rp][pr[t]]);
        }
        float x, y; unpack2(fadd2(a0, a1), x, y);
        ob[(size_t)(2 * p)     * OUT_HW] = x;   // row r0+2p
        ob[(size_t)(2 * p + 1) * OUT_HW] = y;   // row r0+2p+1
    }
}

// ---------------------------------------------------------------------------
// Generic-taps fallback (any taps; table path everywhere).
// ---------------------------------------------------------------------------
__global__ __launch_bounds__(512) void resize_fused_generic(
    const ull*   __restrict__ in,
    const float* __restrict__ wh, const int* __restrict__ fh,
    const float* __restrict__ ww, const int* __restrict__ fw,
    float*       __restrict__ out, int taps)
{
    __shared__ ull   mid2[TOH / 2][MIDW];
    __shared__ float hw_s[MAX_T][TOH];
    __shared__ int   hf_s[MAX_T][TOH];

    const int tid   = threadIdx.x;
    const int col   = tid & 255;
    const int r0    = (tid >> 8) * RPH;
    const int oh0   = blockIdx.x * TOH;
    const int plane = blockIdx.y;

    if (tid < taps * TOH) {
        const int t = tid / TOH, r = tid % TOH;
        hw_s[t][r] = wh[t * OUT_HW + oh0 + r];
        hf_s[t][r] = fh[t * OUT_HW + oh0 + r];
    }
    float wr[MAX_T]; int pr[MAX_T];
    #pragma unroll
    for (int t = 0; t < MAX_T; ++t) {
        if (t < taps) {
            wr[t] = ww[t * OUT_HW + col];
            pr[t] = pos_of(fw[t * OUT_HW + col]);
        } else { wr[t] = 0.f; pr[t] = 0; }
    }
    __syncthreads();

    const ull* base = in + (size_t)plane * IN_HW * 256 + col;
    float sx = 0.f, sy = 0.f;
    for (int j = 0; j < RPH; ++j) {
        const int r = r0 + j;
        float ax = 0.f, ay = 0.f;
        #pragma unroll
        for (int t = 0; t < MAX_T; ++t) {
            if (t < taps) {
                float x, y; unpack2(base[(size_t)hf_s[t][r] * 256], x, y);
                ax = fmaf(hw_s[t][r], x, ax);
                ay = fmaf(hw_s[t][r], y, ay);
            }
        }
        if ((j & 1) == 0) { sx = ax; sy = ay; }
        else {
            const int rp = (r0 >> 1) + (j >> 1);
            mid2[rp][col]         = pack2(sx, ax);
            mid2[rp][col + HALFP] = pack2(sy, ay);
        }
    }
    __syncthreads();

    float* ob = out + ((size_t)plane * OUT_HW + oh0 + r0) * OUT_HW + col;
    for (int p = 0; p < RPH / 2; ++p) {
        const int rp = (r0 >> 1) + p;
        float ax = 0.f, ay = 0.f;
        #pragma unroll
        for (int t = 0; t < MAX_T; ++t) {
            if (t < taps) {
                float x, y; unpack2(mid2[rp][pr[t]], x, y);
                ax = fmaf(wr[t], x, ax);
                ay = fmaf(wr[t], y, ay);
            }
        }
        ob[(size_t)(2 * p)     * OUT_HW] = ax;
        ob[(size_t)(2 * p + 1) * OUT_HW] = ay;
    }
}

// ---------------------------------------------------------------------------
// Inputs (metadata order): in_tensor, w2, fov2 (H axis), w3, fov3 (W axis)
// ---------------------------------------------------------------------------
extern "C" void kernel_launch(void* const* d_in, const int* in_sizes, int n_in,
                              void* d_out, int out_size)
{
    const ull*   in   = (const ull*)  d_in[0];
    const float* w2   = (const float*)d_in[1];
    const int*   fov2 = (const int*)  d_in[2];
    const float* w3   = (const float*)d_in[3];
    const int*   fov3 = (const int*)  d_in[4];
    float* out = (float*)d_out;

    const int taps = in_sizes[1] / OUT_HW;
    dim3 grid(OUT_HW / TOH, BC);                  // (16, 96) = 1536 blocks

    switch (taps) {
    case 6:  resize_fused<6> <<<grid, 512>>>(in, w2, fov2, w3, fov3, out); break;
    case 7:  resize_fused<7> <<<grid, 512>>>(in, w2, fov2, w3, fov3, out); break;
    case 8:  resize_fused<8> <<<grid, 512>>>(in, w2, fov2, w3, fov3, out); break;
    case 9:  resize_fused<9> <<<grid, 512>>>(in, w2, fov2, w3, fov3, out); break;
    case 10: resize_fused<10><<<grid, 512>>>(in, w2, fov2, w3, fov3, out); break;
    case 11: resize_fused<11><<<grid, 512>>>(in, w2, fov2, w3, fov3, out); break;
    case 12: resize_fused<12><<<grid, 512>>>(in, w2, fov2, w3, fov3, out); break;
    default: resize_fused_generic<<<grid, 512>>>(in, w2, fov2, w3, fov3, out, taps); break;
    }
}

// round 10
// speedup vs baseline: 1.1006x; 1.1006x over previous
#include <cuda_runtime.h>
#include <cstdint>

// Problem constants (dataset-fixed: IN=(32,3,512,512), OUT=256, scale=0.5)
#define BC      96
#define IN_HW   512
#define OUT_HW  256
#define TOH     16            // oh rows per block (two 8-row halves)
#define RPH     8             // rows per half
#define MAX_T   12
#define HALFP   260           // odd-column region offset, in 8-byte units
#define MIDW    520           // mid2 row length in 8-byte units

typedef unsigned long long ull;

__device__ __forceinline__ ull pack2(float x, float y) {
    ull r; asm("mov.b64 %0, {%1, %2};" : "=l"(r) : "f"(x), "f"(y)); return r;
}
__device__ __forceinline__ void unpack2(ull v, float& x, float& y) {
    asm("mov.b64 {%0, %1}, %2;" : "=f"(x), "=f"(y) : "l"(v));
}
__device__ __forceinline__ void ffma2(ull& a, ull w, ull v) {
    asm("fma.rn.f32x2 %0, %1, %2, %0;" : "+l"(a) : "l"(w), "l"(v));
}
__device__ __forceinline__ ull fadd2(ull a, ull b) {
    ull r; asm("add.rn.f32x2 %0, %1, %2;" : "=l"(r) : "l"(a), "l"(b)); return r;
}
__device__ __forceinline__ void cp_async16(void* smem_dst, const void* gmem_src) {
    unsigned s = (unsigned)__cvta_generic_to_shared(smem_dst);
    asm volatile("cp.async.cg.shared.global [%0], [%1], 16;" :: "r"(s), "l"(gmem_src));
}

// even/odd split position (8-byte units): fixed-tap gathers become stride-1.
__device__ __forceinline__ int pos_of(int w) { return (w >> 1) + (w & 1) * HALFP; }

// Dynamic smem layout (bytes):
//   [0, 33280)        mid2 : ull[TOH/2][MIDW]
//   [33280, 34304)    hw2  : ull[TAPS][TOH]   (packed (w,w) H weights)
//   [34304, 34816)    hf_s : int[TAPS][TOH]
//   [34816, ...)      in_s : float[NROWS][512]  (cp.async staged input slab)
#define OFF_HW2  33280
#define OFF_HF   34304
#define OFF_IN   34816

// ---------------------------------------------------------------------------
// Fused bicubic downsample, cp.async-staged input.
// Block = 512 threads = one plane x 16 oh x full W.
//   0) cp.async the NROWS x 512 input slab into smem (massive MLP, no regs)
//   1) Phase 1 (H): smem->smem, broadcast-LDS weights, FFMA2, row-pair pack
//   2) Phase 2 (W): conflict-free LDS.64 gathers, coalesced STG
// Edge tiles (mirror folds) use a global-read generic path (as R6).
// ---------------------------------------------------------------------------
template<int TAPS>
__global__ __launch_bounds__(512, 2) void resize_fused(
    const ull*   __restrict__ in,     // (BC, IN_HW, 256) column pairs
    const float* __restrict__ wh, const int* __restrict__ fh,   // H tables
    const float* __restrict__ ww, const int* __restrict__ fw,   // W tables
    float*       __restrict__ out)    // (BC, OUT_HW, OUT_HW)
{
    constexpr int NROWS  = 2 * TOH - 2 + TAPS;        // input rows per slab
    constexpr int CHUNKS = NROWS * (IN_HW * 4 / 16);  // 16B chunks per slab

    extern __shared__ char smem[];
    ull*   mid2 = (ull*)smem;                 // [TOH/2][MIDW]
    ull*   hw2  = (ull*)(smem + OFF_HW2);     // [TAPS][TOH]
    int*   hf_s = (int*)(smem + OFF_HF);      // [TAPS][TOH]
    float* in_s = (float*)(smem + OFF_IN);    // [NROWS][512]
    const ull* ins = (const ull*)in_s;        // [NROWS][256]

    const int tid   = threadIdx.x;            // 0..511
    const int col   = tid & 255;              // owns input cols (2c, 2c+1)
    const int r0    = (tid >> 8) * RPH;       // first oh row of this half
    const int oh0   = blockIdx.x * TOH;
    const int plane = blockIdx.y;

    // ---- 0) Kick off the bulk async copy ASAP ----
    const int b0raw = fh[oh0];                        // uniform LDG broadcast
    int lo = b0raw < 0 ? 0 : b0raw;
    if (lo > IN_HW - NROWS) lo = IN_HW - NROWS;
    {
        // plane stride = 512 * 512 floats * 4 B = 1 MiB; row stride = 2048 B.
        const char* gsrc = (const char*)in
                         + ((size_t)plane * IN_HW * IN_HW
                          + (size_t)lo * IN_HW) * sizeof(float);
        char* sdst = (char*)in_s;
        #pragma unroll
        for (int k = 0; k < (CHUNKS + 511) / 512; ++k) {
            const int i = tid + k * 512;
            if (i < CHUNKS) cp_async16(sdst + i * 16, gsrc + (size_t)i * 16);
        }
        asm volatile("cp.async.commit_group;" ::: "memory");
    }

    // ---- Table loads overlap the bulk copy ----
    if (tid < TAPS * TOH) {
        const int t = tid / TOH, r = tid % TOH;
        const float w = wh[t * OUT_HW + oh0 + r];
        hw2 [t * TOH + r] = pack2(w, w);
        hf_s[t * TOH + r] = fh[t * OUT_HW + oh0 + r];
    }
    __syncthreads();

    // Fast iff H fov is linear: base + 2r + t (interior tiles).
    bool okp = true;
    if (tid < TAPS * TOH) {
        const int t = tid / TOH, r = tid % TOH;
        okp = (hf_s[t * TOH + r] == b0raw + 2 * r + t);
    }
    asm volatile("cp.async.wait_group 0;" ::: "memory");
    const int fast = __syncthreads_and(okp);

    const ull* base = in + (size_t)plane * IN_HW * 256 + col;

    if (fast) {
        // ---- Phase 1 fast: smem input, broadcast-LDS weights, FFMA2 ----
        // fast => b0raw in [0, IN_HW-NROWS] => lo == b0raw, slab row = 2r + t.
        ull stash = 0;
        #pragma unroll
        for (int j = 0; j < RPH; ++j) {
            const int r = r0 + j;
            const ull* rowb = ins + (size_t)(2 * r) * 256 + col;
            ull a0 = 0, a1 = 0;
            #pragma unroll
            for (int t = 0; t < TAPS; ++t) {
                if (t & 1) ffma2(a1, hw2[t * TOH + r], rowb[(size_t)t * 256]);
                else       ffma2(a0, hw2[t * TOH + r], rowb[(size_t)t * 256]);
            }
            const ull acc = fadd2(a0, a1);    // (evenColVal, oddColVal)
            if ((j & 1) == 0) stash = acc;
            else {                            // repack across the row pair
                float ex, ey, ox, oy;
                unpack2(stash, ex, ey);
                unpack2(acc,   ox, oy);
                const int rp = (r0 >> 1) + (j >> 1);
                mid2[rp * MIDW + col]         = pack2(ex, ox);
                mid2[rp * MIDW + col + HALFP] = pack2(ey, oy);
            }
        }
    } else {
        // ---- Phase 1 generic (edge tiles with mirror folds): global reads ----
        float sx = 0.f, sy = 0.f;
        #pragma unroll
        for (int j = 0; j < RPH; ++j) {
            const int r = r0 + j;
            float ax = 0.f, ay = 0.f;
            #pragma unroll
            for (int t = 0; t < TAPS; ++t) {
                float w, wd; unpack2(hw2[t * TOH + r], w, wd);
                float x, y;  unpack2(base[(size_t)hf_s[t * TOH + r] * 256], x, y);
                ax = fmaf(w, x, ax);
                ay = fmaf(w, y, ay);
            }
            if ((j & 1) == 0) { sx = ax; sy = ay; }
            else {
                const int rp = (r0 >> 1) + (j >> 1);
                mid2[rp * MIDW + col]         = pack2(sx, ax);
                mid2[rp * MIDW + col + HALFP] = pack2(sy, ay);
            }
        }
    }

    // Phase-2 per-thread tables AFTER phase 1 (short live range, no spills).
    ull pw[TAPS];
    int pr[TAPS];
    #pragma unroll
    for (int t = 0; t < TAPS; ++t) {
        const float w = ww[t * OUT_HW + col];
        pw[t] = pack2(w, w);
        pr[t] = pos_of(fw[t * OUT_HW + col]);
    }
    __syncthreads();

    // ---- Phase 2: W resize on packed row pairs ----
    float* ob = out + ((size_t)plane * OUT_HW + oh0 + r0) * OUT_HW + col;
    #pragma unroll
    for (int p = 0; p < RPH / 2; ++p) {
        const int rp = (r0 >> 1) + p;
        ull a0 = 0, a1 = 0;
        #pragma unroll
        for (int t = 0; t < TAPS; ++t) {
            if (t & 1) ffma2(a1, pw[t], mid2[rp * MIDW + pr[t]]);
            else       ffma2(a0, pw[t], mid2[rp * MIDW + pr[t]]);
        }
        float x, y; unpack2(fadd2(a0, a1), x, y);
        ob[(size_t)(2 * p)     * OUT_HW] = x;   // row r0+2p
        ob[(size_t)(2 * p + 1) * OUT_HW] = y;   // row r0+2p+1
    }
}

// ---------------------------------------------------------------------------
// Generic-taps fallback (any taps; table path everywhere; static smem).
// ---------------------------------------------------------------------------
__global__ __launch_bounds__(512) void resize_fused_generic(
    const ull*   __restrict__ in,
    const float* __restrict__ wh, const int* __restrict__ fh,
    const float* __restrict__ ww, const int* __restrict__ fw,
    float*       __restrict__ out, int taps)
{
    __shared__ ull   mid2[TOH / 2][MIDW];
    __shared__ float hw_s[MAX_T][TOH];
    __shared__ int   hf_s[MAX_T][TOH];

    const int tid   = threadIdx.x;
    const int col   = tid & 255;
    const int r0    = (tid >> 8) * RPH;
    const int oh0   = blockIdx.x * TOH;
    const int plane = blockIdx.y;

    if (tid < taps * TOH) {
        const int t = tid / TOH, r = tid % TOH;
        hw_s[t][r] = wh[t * OUT_HW + oh0 + r];
        hf_s[t][r] = fh[t * OUT_HW + oh0 + r];
    }
    float wr[MAX_T]; int pr[MAX_T];
    #pragma unroll
    for (int t = 0; t < MAX_T; ++t) {
        if (t < taps) {
            wr[t] = ww[t * OUT_HW + col];
            pr[t] = pos_of(fw[t * OUT_HW + col]);
        } else { wr[t] = 0.f; pr[t] = 0; }
    }
    __syncthreads();

    const ull* base = in + (size_t)plane * IN_HW * 256 + col;
    float sx = 0.f, sy = 0.f;
    for (int j = 0; j < RPH; ++j) {
        const int r = r0 + j;
        float ax = 0.f, ay = 0.f;
        #pragma unroll
        for (int t = 0; t < MAX_T; ++t) {
            if (t < taps) {
                float x, y; unpack2(base[(size_t)hf_s[t][r] * 256], x, y);
                ax = fmaf(hw_s[t][r], x, ax);
                ay = fmaf(hw_s[t][r], y, ay);
            }
        }
        if ((j & 1) == 0) { sx = ax; sy = ay; }
        else {
            const int rp = (r0 >> 1) + (j >> 1);
            mid2[rp][col]         = pack2(sx, ax);
            mid2[rp][col + HALFP] = pack2(sy, ay);
        }
    }
    __syncthreads();

    float* ob = out + ((size_t)plane * OUT_HW + oh0 + r0) * OUT_HW + col;
    for (int p = 0; p < RPH / 2; ++p) {
        const int rp = (r0 >> 1) + p;
        float ax = 0.f, ay = 0.f;
        #pragma unroll
        for (int t = 0; t < MAX_T; ++t) {
            if (t < taps) {
                float x, y; unpack2(mid2[rp][pr[t]], x, y);
                ax = fmaf(wr[t], x, ax);
                ay = fmaf(wr[t], y, ay);
            }
        }
        ob[(size_t)(2 * p)     * OUT_HW] = ax;
        ob[(size_t)(2 * p + 1) * OUT_HW] = ay;
    }
}

// ---------------------------------------------------------------------------
// Inputs (metadata order): in_tensor, w2, fov2 (H axis), w3, fov3 (W axis)
// ---------------------------------------------------------------------------
#define LAUNCH_T(T)                                                            \
    do {                                                                       \
        constexpr int nrows = 2 * TOH - 2 + (T);                               \
        const int smemB = OFF_IN + nrows * IN_HW * 4;                          \
        cudaFuncSetAttribute(resize_fused<(T)>,                                \
            cudaFuncAttributeMaxDynamicSharedMemorySize, smemB);               \
        resize_fused<(T)><<<grid, 512, smemB>>>(in, w2, fov2, w3, fov3, out);  \
    } while (0)

extern "C" void kernel_launch(void* const* d_in, const int* in_sizes, int n_in,
                              void* d_out, int out_size)
{
    const ull*   in   = (const ull*)  d_in[0];
    const float* w2   = (const float*)d_in[1];
    const int*   fov2 = (const int*)  d_in[2];
    const float* w3   = (const float*)d_in[3];
    const int*   fov3 = (const int*)  d_in[4];
    float* out = (float*)d_out;

    const int taps = in_sizes[1] / OUT_HW;
    dim3 grid(OUT_HW / TOH, BC);                  // (16, 96) = 1536 blocks

    switch (taps) {
    case 6:  LAUNCH_T(6);  break;
    case 7:  LAUNCH_T(7);  break;
    case 8:  LAUNCH_T(8);  break;
    case 9:  LAUNCH_T(9);  break;
    case 10: LAUNCH_T(10); break;
    case 11: LAUNCH_T(11); break;
    case 12: LAUNCH_T(12); break;
    default: resize_fused_generic<<<grid, 512>>>(in, w2, fov2, w3, fov3, out, taps); break;
    }
}

// round 11
// speedup vs baseline: 1.1634x; 1.0570x over previous
#include <cuda_runtime.h>
#include <cstdint>

// Problem constants (dataset-fixed: IN=(32,3,512,512), OUT=256, scale=0.5)
#define BC      96
#define IN_HW   512
#define OUT_HW  256
#define TOH     16            // oh rows per block (two 8-row halves)
#define RPH     8             // rows per half
#define MAX_T   12
#define HALFP   260           // odd-column region offset, in 8-byte units
#define MIDW    520           // mid2 row length in 8-byte units

typedef unsigned long long ull;

__device__ __forceinline__ ull pack2(float x, float y) {
    ull r; asm("mov.b64 %0, {%1, %2};" : "=l"(r) : "f"(x), "f"(y)); return r;
}
__device__ __forceinline__ void unpack2(ull v, float& x, float& y) {
    asm("mov.b64 {%0, %1}, %2;" : "=f"(x), "=f"(y) : "l"(v));
}
__device__ __forceinline__ void ffma2(ull& a, ull w, ull v) {
    asm("fma.rn.f32x2 %0, %1, %2, %0;" : "+l"(a) : "l"(w), "l"(v));
}
__device__ __forceinline__ ull fadd2(ull a, ull b) {
    ull r; asm("add.rn.f32x2 %0, %1, %2;" : "=l"(r) : "l"(a), "l"(b)); return r;
}
__device__ __forceinline__ void cp_async16(void* smem_dst, const void* gmem_src) {
    unsigned s = (unsigned)__cvta_generic_to_shared(smem_dst);
    asm volatile("cp.async.cg.shared.global [%0], [%1], 16;" :: "r"(s), "l"(gmem_src));
}

// even/odd split position (8-byte units): fixed-tap gathers become stride-1.
__device__ __forceinline__ int pos_of(int w) { return (w >> 1) + (w & 1) * HALFP; }

// Dynamic smem layout (bytes):
//   [0, 33280)        mid2 : ull[TOH/2][MIDW]
//   [33280, 34304)    hw2  : ull[TAPS][TOH]   (packed (w,w) H weights)
//   [34304, 34816)    hf_s : int[TAPS][TOH]
//   [34816, ...)      in_s : float[NROWS][512]  (cp.async staged input slab)
#define OFF_HW2  33280
#define OFF_HF   34304
#define OFF_IN   34816

// ---------------------------------------------------------------------------
// Fused bicubic downsample: cp.async-staged input + register sliding window.
// Block = 512 threads = one plane x 16 oh x full W.
//   0) cp.async the NROWS x 512 input slab into smem (async-engine MLP)
//   1) Phase 1 (H): circular REGISTER window over the smem slab -- each
//      staged byte crosses the LDS crossbar exactly once; FFMA2 math.
//   2) Phase 2 (W): conflict-free LDS.64 gathers on packed row pairs.
// Edge tiles (mirror folds) use a global-read generic path.
// ---------------------------------------------------------------------------
template<int TAPS>
__global__ __launch_bounds__(512) void resize_fused(
    const ull*   __restrict__ in,     // (BC, IN_HW, 256) column pairs
    const float* __restrict__ wh, const int* __restrict__ fh,   // H tables
    const float* __restrict__ ww, const int* __restrict__ fw,   // W tables
    float*       __restrict__ out)    // (BC, OUT_HW, OUT_HW)
{
    constexpr int NROWS  = 2 * TOH - 2 + TAPS;        // input rows per slab
    constexpr int CHUNKS = NROWS * (IN_HW * 4 / 16);  // 16B chunks per slab

    extern __shared__ char smem[];
    ull*   mid2 = (ull*)smem;                 // [TOH/2][MIDW]
    ull*   hw2  = (ull*)(smem + OFF_HW2);     // [TAPS][TOH]
    int*   hf_s = (int*)(smem + OFF_HF);      // [TAPS][TOH]
    float* in_s = (float*)(smem + OFF_IN);    // [NROWS][512]
    const ull* ins = (const ull*)in_s;        // [NROWS][256]

    const int tid   = threadIdx.x;            // 0..511
    const int col   = tid & 255;              // owns input cols (2c, 2c+1)
    const int r0    = (tid >> 8) * RPH;       // first oh row of this half
    const int oh0   = blockIdx.x * TOH;
    const int plane = blockIdx.y;

    // ---- 0) Kick off the bulk async copy ASAP ----
    const int b0raw = fh[oh0];                        // uniform LDG broadcast
    int lo = b0raw < 0 ? 0 : b0raw;
    if (lo > IN_HW - NROWS) lo = IN_HW - NROWS;
    {
        const char* gsrc = (const char*)in
                         + ((size_t)plane * IN_HW * IN_HW
                          + (size_t)lo * IN_HW) * sizeof(float);
        char* sdst = (char*)in_s;
        #pragma unroll
        for (int k = 0; k < (CHUNKS + 511) / 512; ++k) {
            const int i = tid + k * 512;
            if (i < CHUNKS) cp_async16(sdst + i * 16, gsrc + (size_t)i * 16);
        }
        asm volatile("cp.async.commit_group;" ::: "memory");
    }

    // ---- Table loads overlap the bulk copy ----
    if (tid < TAPS * TOH) {
        const int t = tid / TOH, r = tid % TOH;
        const float w = wh[t * OUT_HW + oh0 + r];
        hw2 [t * TOH + r] = pack2(w, w);
        hf_s[t * TOH + r] = fh[t * OUT_HW + oh0 + r];
    }
    __syncthreads();

    // Fast iff H fov is linear: base + 2r + t (interior tiles).
    bool okp = true;
    if (tid < TAPS * TOH) {
        const int t = tid / TOH, r = tid % TOH;
        okp = (hf_s[t * TOH + r] == b0raw + 2 * r + t);
    }
    asm volatile("cp.async.wait_group 0;" ::: "memory");
    const int fast = __syncthreads_and(okp);

    const ull* base = in + (size_t)plane * IN_HW * 256 + col;

    if (fast) {
        // ---- Phase 1 fast: circular register window over the smem slab ----
        // fast => lo == b0raw; slab row for (r, t) = 2r + t.
        const ull* sb = ins + col;
        ull v[TAPS];
        #pragma unroll
        for (int t = 0; t < TAPS; ++t)
            v[t] = sb[(size_t)(2 * r0 + t) * 256];

        ull stash = 0;
        #pragma unroll
        for (int j = 0; j < RPH; ++j) {
            const int r = r0 + j;
            ull a0 = 0, a1 = 0;
            ffma2(a0, hw2[0 * TOH + r], v[(2 * j)     % TAPS]);
            ffma2(a1, hw2[1 * TOH + r], v[(2 * j + 1) % TAPS]);
            if (j < RPH - 1) {                // refill the two consumed slots
                v[(2 * j)     % TAPS] = sb[(size_t)(2 * r0 + 2 * j + TAPS)     * 256];
                v[(2 * j + 1) % TAPS] = sb[(size_t)(2 * r0 + 2 * j + TAPS + 1) * 256];
            }
            #pragma unroll
            for (int t = 2; t < TAPS; ++t) {
                if (t & 1) ffma2(a1, hw2[t * TOH + r], v[(2 * j + t) % TAPS]);
                else       ffma2(a0, hw2[t * TOH + r], v[(2 * j + t) % TAPS]);
            }
            const ull acc = fadd2(a0, a1);    // (evenColVal, oddColVal)
            if ((j & 1) == 0) stash = acc;
            else {                            // repack across the row pair
                float ex, ey, ox, oy;
                unpack2(stash, ex, ey);
                unpack2(acc,   ox, oy);
                const int rp = (r0 >> 1) + (j >> 1);
                mid2[rp * MIDW + col]         = pack2(ex, ox);
                mid2[rp * MIDW + col + HALFP] = pack2(ey, oy);
            }
        }
    } else {
        // ---- Phase 1 generic (edge tiles with mirror folds): global reads ----
        float sx = 0.f, sy = 0.f;
        #pragma unroll
        for (int j = 0; j < RPH; ++j) {
            const int r = r0 + j;
            float ax = 0.f, ay = 0.f;
            #pragma unroll
            for (int t = 0; t < TAPS; ++t) {
                float w, wd; unpack2(hw2[t * TOH + r], w, wd);
                float x, y;  unpack2(base[(size_t)hf_s[t * TOH + r] * 256], x, y);
                ax = fmaf(w, x, ax);
                ay = fmaf(w, y, ay);
            }
            if ((j & 1) == 0) { sx = ax; sy = ay; }
            else {
                const int rp = (r0 >> 1) + (j >> 1);
                mid2[rp * MIDW + col]         = pack2(sx, ax);
                mid2[rp * MIDW + col + HALFP] = pack2(sy, ay);
            }
        }
    }

    // Phase-2 per-thread tables AFTER phase 1 (short live range, no spills).
    ull pw[TAPS];
    int pr[TAPS];
    #pragma unroll
    for (int t = 0; t < TAPS; ++t) {
        const float w = ww[t * OUT_HW + col];
        pw[t] = pack2(w, w);
        pr[t] = pos_of(fw[t * OUT_HW + col]);
    }
    __syncthreads();

    // ---- Phase 2: W resize on packed row pairs ----
    float* ob = out + ((size_t)plane * OUT_HW + oh0 + r0) * OUT_HW + col;
    #pragma unroll
    for (int p = 0; p < RPH / 2; ++p) {
        const int rp = (r0 >> 1) + p;
        ull a0 = 0, a1 = 0;
        #pragma unroll
        for (int t = 0; t < TAPS; ++t) {
            if (t & 1) ffma2(a1, pw[t], mid2[rp * MIDW + pr[t]]);
            else       ffma2(a0, pw[t], mid2[rp * MIDW + pr[t]]);
        }
        float x, y; unpack2(fadd2(a0, a1), x, y);
        ob[(size_t)(2 * p)     * OUT_HW] = x;   // row r0+2p
        ob[(size_t)(2 * p + 1) * OUT_HW] = y;   // row r0+2p+1
    }
}

// ---------------------------------------------------------------------------
// Generic-taps fallback (any taps; table path everywhere; static smem).
// ---------------------------------------------------------------------------
__global__ __launch_bounds__(512) void resize_fused_generic(
    const ull*   __restrict__ in,
    const float* __restrict__ wh, const int* __restrict__ fh,
    const float* __restrict__ ww, const int* __restrict__ fw,
    float*       __restrict__ out, int taps)
{
    __shared__ ull   mid2[TOH / 2][MIDW];
    __shared__ float hw_s[MAX_T][TOH];
    __shared__ int   hf_s[MAX_T][TOH];

    const int tid   = threadIdx.x;
    const int col   = tid & 255;
    const int r0    = (tid >> 8) * RPH;
    const int oh0   = blockIdx.x * TOH;
    const int plane = blockIdx.y;

    if (tid < taps * TOH) {
        const int t = tid / TOH, r = tid % TOH;
        hw_s[t][r] = wh[t * OUT_HW + oh0 + r];
        hf_s[t][r] = fh[t * OUT_HW + oh0 + r];
    }
    float wr[MAX_T]; int pr[MAX_T];
    #pragma unroll
    for (int t = 0; t < MAX_T; ++t) {
        if (t < taps) {
            wr[t] = ww[t * OUT_HW + col];
            pr[t] = pos_of(fw[t * OUT_HW + col]);
        } else { wr[t] = 0.f; pr[t] = 0; }
    }
    __syncthreads();

    const ull* base = in + (size_t)plane * IN_HW * 256 + col;
    float sx = 0.f, sy = 0.f;
    for (int j = 0; j < RPH; ++j) {
        const int r = r0 + j;
        float ax = 0.f, ay = 0.f;
        #pragma unroll
        for (int t = 0; t < MAX_T; ++t) {
            if (t < taps) {
                float x, y; unpack2(base[(size_t)hf_s[t][r] * 256], x, y);
                ax = fmaf(hw_s[t][r], x, ax);
                ay = fmaf(hw_s[t][r], y, ay);
            }
        }
        if ((j & 1) == 0) { sx = ax; sy = ay; }
        else {
            const int rp = (r0 >> 1) + (j >> 1);
            mid2[rp][col]         = pack2(sx, ax);
            mid2[rp][col + HALFP] = pack2(sy, ay);
        }
    }
    __syncthreads();

    float* ob = out + ((size_t)plane * OUT_HW + oh0 + r0) * OUT_HW + col;
    for (int p = 0; p < RPH / 2; ++p) {
        const int rp = (r0 >> 1) + p;
        float ax = 0.f, ay = 0.f;
        #pragma unroll
        for (int t = 0; t < MAX_T; ++t) {
            if (t < taps) {
                float x, y; unpack2(mid2[rp][pr[t]], x, y);
                ax = fmaf(wr[t], x, ax);
                ay = fmaf(wr[t], y, ay);
            }
        }
        ob[(size_t)(2 * p)     * OUT_HW] = ax;
        ob[(size_t)(2 * p + 1) * OUT_HW] = ay;
    }
}

// ---------------------------------------------------------------------------
// Inputs (metadata order): in_tensor, w2, fov2 (H axis), w3, fov3 (W axis)
// ---------------------------------------------------------------------------
#define LAUNCH_T(T)                                                            \
    do {                                                                       \
        constexpr int nrows = 2 * TOH - 2 + (T);                               \
        const int smemB = OFF_IN + nrows * IN_HW * 4;                          \
        cudaFuncSetAttribute(resize_fused<(T)>,                                \
            cudaFuncAttributeMaxDynamicSharedMemorySize, smemB);               \
        resize_fused<(T)><<<grid, 512, smemB>>>(in, w2, fov2, w3, fov3, out);  \
    } while (0)

extern "C" void kernel_launch(void* const* d_in, const int* in_sizes, int n_in,
                              void* d_out, int out_size)
{
    const ull*   in   = (const ull*)  d_in[0];
    const float* w2   = (const float*)d_in[1];
    const int*   fov2 = (const int*)  d_in[2];
    const float* w3   = (const float*)d_in[3];
    const int*   fov3 = (const int*)  d_in[4];
    float* out = (float*)d_out;

    const int taps = in_sizes[1] / OUT_HW;
    dim3 grid(OUT_HW / TOH, BC);                  // (16, 96) = 1536 blocks

    switch (taps) {
    case 6:  LAUNCH_T(6);  break;
    case 7:  LAUNCH_T(7);  break;
    case 8:  LAUNCH_T(8);  break;
    case 9:  LAUNCH_T(9);  break;
    case 10: LAUNCH_T(10); break;
    case 11: LAUNCH_T(11); break;
    case 12: LAUNCH_T(12); break;
    default: resize_fused_generic<<<grid, 512>>>(in, w2, fov2, w3, fov3, out, taps); break;
    }
}

// round 13
// speedup vs baseline: 1.2293x; 1.0567x over previous
#include <cuda_runtime.h>
#include <cstdint>

// Problem constants (dataset-fixed: IN=(32,3,512,512), OUT=256, scale=0.5)
#define BC      96
#define IN_HW   512
#define OUT_HW  256
#define TOH     8             // oh rows per block (two 4-row halves)
#define RPH     4             // rows per half (even!)
#define MAX_T   12
#define HALFP   260           // odd-column region offset, in 8-byte units
#define MIDW    520           // mid2 row length in 8-byte units

typedef unsigned long long ull;

__device__ __forceinline__ ull pack2(float x, float y) {
    ull r; asm("mov.b64 %0, {%1, %2};" : "=l"(r) : "f"(x), "f"(y)); return r;
}
__device__ __forceinline__ void unpack2(ull v, float& x, float& y) {
    asm("mov.b64 {%0, %1}, %2;" : "=f"(x), "=f"(y) : "l"(v));
}
__device__ __forceinline__ void ffma2(ull& a, ull w, ull v) {
    asm("fma.rn.f32x2 %0, %1, %2, %0;" : "+l"(a) : "l"(w), "l"(v));
}
__device__ __forceinline__ ull fadd2(ull a, ull b) {
    ull r; asm("add.rn.f32x2 %0, %1, %2;" : "=l"(r) : "l"(a), "l"(b)); return r;
}
__device__ __forceinline__ void cp_async16(void* smem_dst, const void* gmem_src) {
    unsigned s = (unsigned)__cvta_generic_to_shared(smem_dst);
    asm volatile("cp.async.cg.shared.global [%0], [%1], 16;" :: "r"(s), "l"(gmem_src));
}

// even/odd split position (8-byte units): fixed-tap gathers become stride-1.
__device__ __forceinline__ int pos_of(int w) { return (w >> 1) + (w & 1) * HALFP; }

// Dynamic smem layout (bytes), TOH = 8:
//   [0, 16640)        mid2 : ull[TOH/2][MIDW]              (4*520*8)
//   [16640, 17408)    hw2  : ull[MAX_T][TOH]               (12*8*8)
//   [17408, 17792)    hf_s : int[MAX_T][TOH]               (12*8*4)
//   [17792, ...)      in_s : float[NROWS][512]  (cp.async staged input slab)
#define OFF_HW2  16640
#define OFF_HF   17408
#define OFF_IN   17792

// ---------------------------------------------------------------------------
// Fused bicubic downsample: cp.async-staged input + register sliding window.
// TOH=8 tile -> 62 KB smem/block -> 3 blocks/SM: stage/compute phases of
// co-resident blocks overlap, filling the DRAM duty-cycle gaps.
// Block = 512 threads = one plane x 8 oh x full W, two 4-row halves.
//   0) cp.async the NROWS x 512 input slab into smem (async-engine MLP)
//   1) Phase 1 (H): circular register window over the smem slab (each byte
//      crosses the LDS crossbar once), broadcast-LDS weights, FFMA2.
//   2) Phase 2 (W): conflict-free LDS.64 gathers on packed row pairs.
// Edge tiles (mirror folds) use a global-read generic path.
// ---------------------------------------------------------------------------
template<int TAPS>
__global__ __launch_bounds__(512) void resize_fused(
    const ull*   __restrict__ in,     // (BC, IN_HW, 256) column pairs
    const float* __restrict__ wh, const int* __restrict__ fh,   // H tables
    const float* __restrict__ ww, const int* __restrict__ fw,   // W tables
    float*       __restrict__ out)    // (BC, OUT_HW, OUT_HW)
{
    constexpr int NROWS  = 2 * TOH - 2 + TAPS;        // input rows per slab
    constexpr int CHUNKS = NROWS * (IN_HW * 4 / 16);  // 16B chunks per slab

    extern __shared__ char smem[];
    ull*   mid2 = (ull*)smem;                 // [TOH/2][MIDW]
    ull*   hw2  = (ull*)(smem + OFF_HW2);     // [TAPS][TOH]
    int*   hf_s = (int*)(smem + OFF_HF);      // [TAPS][TOH]
    float* in_s = (float*)(smem + OFF_IN);    // [NROWS][512]
    const ull* ins = (const ull*)in_s;        // [NROWS][256]

    const int tid   = threadIdx.x;            // 0..511
    const int col   = tid & 255;              // owns input cols (2c, 2c+1)
    const int r0    = (tid >> 8) * RPH;       // first oh row of this half
    const int oh0   = blockIdx.x * TOH;
    const int plane = blockIdx.y;

    // ---- 0) Kick off the bulk async copy ASAP ----
    const int b0raw = fh[oh0];                        // uniform LDG broadcast
    int lo = b0raw < 0 ? 0 : b0raw;
    if (lo > IN_HW - NROWS) lo = IN_HW - NROWS;
    {
        const char* gsrc = (const char*)in
                         + ((size_t)plane * IN_HW * IN_HW
                          + (size_t)lo * IN_HW) * sizeof(float);
        char* sdst = (char*)in_s;
        #pragma unroll
        for (int k = 0; k < (CHUNKS + 511) / 512; ++k) {
            const int i = tid + k * 512;
            if (i < CHUNKS) cp_async16(sdst + (size_t)i * 16, gsrc + (size_t)i * 16);
        }
        asm volatile("cp.async.commit_group;" ::: "memory");
    }

    // ---- Table loads overlap the bulk copy ----
    if (tid < TAPS * TOH) {
        const int t = tid / TOH, r = tid % TOH;
        const float w = wh[t * OUT_HW + oh0 + r];
        hw2 [t * TOH + r] = pack2(w, w);
        hf_s[t * TOH + r] = fh[t * OUT_HW + oh0 + r];
    }
    __syncthreads();

    // Fast iff H fov is linear: base + 2r + t (interior tiles => lo == b0raw).
    bool okp = true;
    if (tid < TAPS * TOH) {
        const int t = tid / TOH, r = tid % TOH;
        okp = (hf_s[t * TOH + r] == b0raw + 2 * r + t);
    }
    asm volatile("cp.async.wait_group 0;" ::: "memory");
    const int fast = __syncthreads_and(okp);    // barrier: all copies visible

    const ull* base = in + (size_t)plane * IN_HW * 256 + col;

    if (fast) {
        // ---- Phase 1 fast: circular register window over the smem slab ----
        // fast => lo == b0raw; slab row for (r, t) = 2r + t.
        const ull* sb = ins + col;
        ull v[TAPS];
        #pragma unroll
        for (int t = 0; t < TAPS; ++t)
            v[t] = sb[(size_t)(2 * r0 + t) * 256];

        ull stash = 0;
        #pragma unroll
        for (int j = 0; j < RPH; ++j) {
            const int r = r0 + j;
            ull a0 = 0, a1 = 0;
            ffma2(a0, hw2[0 * TOH + r], v[(2 * j)     % TAPS]);
            ffma2(a1, hw2[1 * TOH + r], v[(2 * j + 1) % TAPS]);
            if (j < RPH - 1) {                // refill the two consumed slots
                v[(2 * j)     % TAPS] = sb[(size_t)(2 * r0 + 2 * j + TAPS)     * 256];
                v[(2 * j + 1) % TAPS] = sb[(size_t)(2 * r0 + 2 * j + TAPS + 1) * 256];
            }
            #pragma unroll
            for (int t = 2; t < TAPS; ++t) {
                if (t & 1) ffma2(a1, hw2[t * TOH + r], v[(2 * j + t) % TAPS]);
                else       ffma2(a0, hw2[t * TOH + r], v[(2 * j + t) % TAPS]);
            }
            const ull acc = fadd2(a0, a1);    // (evenColVal, oddColVal)
            if ((j & 1) == 0) stash = acc;
            else {                            // repack across the row pair
                float ex, ey, ox, oy;
                unpack2(stash, ex, ey);
                unpack2(acc,   ox, oy);
                const int rp = (r0 >> 1) + (j >> 1);
                mid2[rp * MIDW + col]         = pack2(ex, ox);
                mid2[rp * MIDW + col + HALFP] = pack2(ey, oy);
            }
        }
    } else {
        // ---- Phase 1 generic (edge tiles with mirror folds): global reads ----
        float sx = 0.f, sy = 0.f;
        #pragma unroll
        for (int j = 0; j < RPH; ++j) {
            const int r = r0 + j;
            float ax = 0.f, ay = 0.f;
            #pragma unroll
            for (int t = 0; t < TAPS; ++t) {
                float w, wd; unpack2(hw2[t * TOH + r], w, wd);
                float x, y;  unpack2(base[(size_t)hf_s[t * TOH + r] * 256], x, y);
                ax = fmaf(w, x, ax);
                ay = fmaf(w, y, ay);
            }
            if ((j & 1) == 0) { sx = ax; sy = ay; }
            else {
                const int rp = (r0 >> 1) + (j >> 1);
                mid2[rp * MIDW + col]         = pack2(sx, ax);
                mid2[rp * MIDW + col + HALFP] = pack2(sy, ay);
            }
        }
    }

    // Phase-2 per-thread tables AFTER phase 1 (short live range, no spills).
    ull pw[TAPS];
    int pr[TAPS];
    #pragma unroll
    for (int t = 0; t < TAPS; ++t) {
        const float w = ww[t * OUT_HW + col];
        pw[t] = pack2(w, w);
        pr[t] = pos_of(fw[t * OUT_HW + col]);
    }
    __syncthreads();

    // ---- Phase 2: W resize on packed row pairs ----
    float* ob = out + ((size_t)plane * OUT_HW + oh0 + r0) * OUT_HW + col;
    #pragma unroll
    for (int p = 0; p < RPH / 2; ++p) {
        const int rp = (r0 >> 1) + p;
        ull a0 = 0, a1 = 0;
        #pragma unroll
        for (int t = 0; t < TAPS; ++t) {
            if (t & 1) ffma2(a1, pw[t], mid2[rp * MIDW + pr[t]]);
            else       ffma2(a0, pw[t], mid2[rp * MIDW + pr[t]]);
        }
        float x, y; unpack2(fadd2(a0, a1), x, y);
        ob[(size_t)(2 * p)     * OUT_HW] = x;   // row r0+2p
        ob[(size_t)(2 * p + 1) * OUT_HW] = y;   // row r0+2p+1
    }
}

// ---------------------------------------------------------------------------
// Generic-taps fallback (any taps; table path everywhere; static smem).
// ---------------------------------------------------------------------------
__global__ __launch_bounds__(512) void resize_fused_generic(
    const ull*   __restrict__ in,
    const float* __restrict__ wh, const int* __restrict__ fh,
    const float* __restrict__ ww, const int* __restrict__ fw,
    float*       __restrict__ out, int taps)
{
    __shared__ ull   mid2[TOH / 2][MIDW];
    __shared__ float hw_s[MAX_T][TOH];
    __shared__ int   hf_s[MAX_T][TOH];

    const int tid   = threadIdx.x;
    const int col   = tid & 255;
    const int r0    = (tid >> 8) * RPH;
    const int oh0   = blockIdx.x * TOH;
    const int plane = blockIdx.y;

    if (tid < taps * TOH) {
        const int t = tid / TOH, r = tid % TOH;
        hw_s[t][r] = wh[t * OUT_HW + oh0 + r];
        hf_s[t][r] = fh[t * OUT_HW + oh0 + r];
    }
    float wr[MAX_T]; int pr[MAX_T];
    #pragma unroll
    for (int t = 0; t < MAX_T; ++t) {
        if (t < taps) {
            wr[t] = ww[t * OUT_HW + col];
            pr[t] = pos_of(fw[t * OUT_HW + col]);
        } else { wr[t] = 0.f; pr[t] = 0; }
    }
    __syncthreads();

    const ull* base = in + (size_t)plane * IN_HW * 256 + col;
    float sx = 0.f, sy = 0.f;
    for (int j = 0; j < RPH; ++j) {
        const int r = r0 + j;
        float ax = 0.f, ay = 0.f;
        #pragma unroll
        for (int t = 0; t < MAX_T; ++t) {
            if (t < taps) {
                float x, y; unpack2(base[(size_t)hf_s[t][r] * 256], x, y);
                ax = fmaf(hw_s[t][r], x, ax);
                ay = fmaf(hw_s[t][r], y, ay);
            }
        }
        if ((j & 1) == 0) { sx = ax; sy = ay; }
        else {
            const int rp = (r0 >> 1) + (j >> 1);
            mid2[rp][col]         = pack2(sx, ax);
            mid2[rp][col + HALFP] = pack2(sy, ay);
        }
    }
    __syncthreads();

    float* ob = out + ((size_t)plane * OUT_HW + oh0 + r0) * OUT_HW + col;
    for (int p = 0; p < RPH / 2; ++p) {
        const int rp = (r0 >> 1) + p;
        float ax = 0.f, ay = 0.f;
        #pragma unroll
        for (int t = 0; t < MAX_T; ++t) {
            if (t < taps) {
                float x, y; unpack2(mid2[rp][pr[t]], x, y);
                ax = fmaf(wr[t], x, ax);
                ay = fmaf(wr[t], y, ay);
            }
        }
        ob[(size_t)(2 * p)     * OUT_HW] = ax;
        ob[(size_t)(2 * p + 1) * OUT_HW] = ay;
    }
}

// ---------------------------------------------------------------------------
// Inputs (metadata order): in_tensor, w2, fov2 (H axis), w3, fov3 (W axis)
// ---------------------------------------------------------------------------
#define LAUNCH_T(T)                                                            \
    do {                                                                       \
        constexpr int nrows = 2 * TOH - 2 + (T);                               \
        const int smemB = OFF_IN + nrows * IN_HW * 4;                          \
        cudaFuncSetAttribute(resize_fused<(T)>,                                \
            cudaFuncAttributeMaxDynamicSharedMemorySize, smemB);               \
        resize_fused<(T)><<<grid, 512, smemB>>>(in, w2, fov2, w3, fov3, out);  \
    } while (0)

extern "C" void kernel_launch(void* const* d_in, const int* in_sizes, int n_in,
                              void* d_out, int out_size)
{
    const ull*   in   = (const ull*)  d_in[0];
    const float* w2   = (const float*)d_in[1];
    const int*   fov2 = (const int*)  d_in[2];
    const float* w3   = (const float*)d_in[3];
    const int*   fov3 = (const int*)  d_in[4];
    float* out = (float*)d_out;

    const int taps = in_sizes[1] / OUT_HW;
    dim3 grid(OUT_HW / TOH, BC);                  // (32, 96) = 3072 blocks

    switch (taps) {
    case 6:  LAUNCH_T(6);  break;
    case 7:  LAUNCH_T(7);  break;
    case 8:  LAUNCH_T(8);  break;
    case 9:  LAUNCH_T(9);  break;
    case 10: LAUNCH_T(10); break;
    case 11: LAUNCH_T(11); break;
    case 12: LAUNCH_T(12); break;
    default: resize_fused_generic<<<grid, 512>>>(in, w2, fov2, w3, fov3, out, taps); break;
    }
}